// round 15
// baseline (speedup 1.0000x reference)
#include <cuda_runtime.h>
#include <cstdint>

// Fixed problem geometry: H=W=2048, step=2 -> nu=nv=1024, N=2^20 nodes.
constexpr int NU = 1024;
constexpr int NV = 1024;
constexpr int N  = NU * NV;
constexpr int W  = 2048;
constexpr int ROWF = 6 * W;        // floats per pixel row (12288)

// Output layout (floats): pts[3N] nrm[3N] radii[N] lens[4N] areas[2N]
constexpr int OFF_PTS  = 0;
constexpr int OFF_NRM  = 3 * N;
constexpr int OFF_RAD  = 6 * N;
constexpr int OFF_LEN  = 7 * N;
constexpr int OFF_AREA = 11 * N;

constexpr int TPB = 256;

__device__ __forceinline__ float fast_sqrt(float x) {
    return x * rsqrtf(fmaxf(x, 1e-30f));   // x==0 -> 0, not NaN
}

struct F3 { float x, y, z; };

__device__ __forceinline__ float dist3(const F3& a, const F3& b) {
    float dx = a.x - b.x, dy = a.y - b.y, dz = a.z - b.z;
    return fast_sqrt(dx * dx + dy * dy + dz * dz);
}

__device__ __forceinline__ F3 sub3(const F3& a, const F3& b) {
    F3 r; r.x = a.x - b.x; r.y = a.y - b.y; r.z = a.z - b.z; return r;
}

__device__ __forceinline__ float cross_area(const F3& u, const F3& v) {
    float cx = u.y * v.z - u.z * v.y;
    float cy = u.z * v.x - u.x * v.z;
    float cz = u.x * v.y - u.y * v.x;
    return 0.5f * fast_sqrt(cx * cx + cy * cy + cz * cz + 1e-13f);
}

__device__ __forceinline__ F3 loadA(const float* __restrict__ p, int jv, int iu) {
    int off = jv * ROWF + iu * 6;              // anchor pixel, 8B aligned
    float2 ab = *reinterpret_cast<const float2*>(p + off);
    F3 r; r.x = ab.x; r.y = ab.y; r.z = p[off + 2];
    return r;
}

__device__ __forceinline__ F3 shup3(const F3& v) {
    F3 r;
    r.x = __shfl_up_sync(0xffffffffu, v.x, 1);
    r.y = __shfl_up_sync(0xffffffffu, v.y, 1);
    r.z = __shfl_up_sync(0xffffffffu, v.z, 1);
    return r;
}
__device__ __forceinline__ F3 shdn3(const F3& v) {
    F3 r;
    r.x = __shfl_down_sync(0xffffffffu, v.x, 1);
    r.y = __shfl_down_sync(0xffffffffu, v.y, 1);
    r.z = __shfl_down_sync(0xffffffffu, v.z, 1);
    return r;
}

// ---------------------------------------------------------------------------
// One node per thread; warp = 32 consecutive iu within one grid row.
// Neighbor points via warp shuffles; lanes 0/31 patch halos via LDG.
// min-blocks 7 caps regs at 36 -> 56 warps/SM theoretical occupancy.
// ---------------------------------------------------------------------------
__global__ __launch_bounds__(TPB, 7)
void k_warp(const float* __restrict__ cand,
            const float* __restrict__ cnrm,
            float* __restrict__ out) {
    const int k    = blockIdx.x * TPB + threadIdx.x;
    const int lane = threadIdx.x & 31;
    const int iu   = k & (NU - 1);
    const int jv   = k >> 10;

    const bool re = iu < NU - 1;
    const bool de = jv < NV - 1;
    const bool le = iu > 0;
    const bool ue = jv > 0;
    const bool rd = re && de;

    const int jU = ue ? jv - 1 : 0;    // clamped, flag-guarded
    const int jD = de ? jv + 1 : jv;

    // --- own-column point loads (3 rows) + normal ---
    F3 P0 = loadA(cand, jv, iu);
    F3 PD = loadA(cand, jD, iu);
    F3 PU = loadA(cand, jU, iu);
    F3 NR = loadA(cnrm, jv, iu);

    // pts / nrm out immediately (shortens live ranges)
    {
        const int p3 = OFF_PTS + 3 * k;
        out[p3 + 0] = P0.x; out[p3 + 1] = P0.y; out[p3 + 2] = P0.z;
        const int n3 = OFF_NRM + 3 * k;
        out[n3 + 0] = NR.x; out[n3 + 1] = NR.y; out[n3 + 2] = NR.z;
    }

    // --- neighbor points via shuffles; halo patch by LDG ---
    F3 PR  = shdn3(P0);   // (iu+1, jv)
    F3 PG  = shdn3(PD);   // (iu+1, jD)
    F3 PUR = shdn3(PU);   // (iu+1, jU)
    F3 PUL = shup3(PU);   // (iu-1, jU)
    if (lane == 31) {
        int iR = re ? iu + 1 : iu;     // clamp; re-guarded
        PR  = loadA(cand, jv, iR);
        PG  = loadA(cand, jD, iR);
        PUR = loadA(cand, jU, iR);
    }

    // --- own distances ---
    float dR = dist3(P0, PR);
    float dG = dist3(P0, PG);
    float dD = dist3(P0, PD);
    float dA = dist3(PR, PD);

    // --- left incident distances via shuffle; lane 0 patches all left data ---
    float dRl = __shfl_up_sync(0xffffffffu, dR, 1);   // R[k-1]
    float dAl = __shfl_up_sync(0xffffffffu, dA, 1);   // A[k-1]
    if (lane == 0) {
        int iL = le ? iu - 1 : 0;     // clamp; le-guarded
        F3 Pl  = loadA(cand, jv, iL);
        F3 PDl = loadA(cand, jD, iL);
        PUL    = loadA(cand, jU, iL);
        dRl = dist3(Pl, P0);
        dAl = dist3(P0, PDl);          // A[k-1] = |p(k) - p(k-1+NU)|
    }

    // --- up-row incident distances (ue-guarded) ---
    float dDu  = dist3(PU,  P0);   // D[k-NU]
    float dAu  = dist3(PUR, P0);   // A[k-NU]
    float dGul = dist3(PUL, P0);   // G[k-NU-1]

    // --- areas ---
    float a0 = cross_area(sub3(PR, P0), sub3(PG, P0));
    float a1 = cross_area(sub3(PG, P0), sub3(PD, P0));

    // --- radii: sum of incident edges; count via closed algebra ---
    float sum = 0.0f;
    if (re) sum += dR;
    if (rd) sum += dG;
    if (de) sum += dD;
    if (le && de) sum += dAl;
    if (le)       sum += dRl;
    if (le && ue) sum += dGul;
    if (ue)       sum += dDu;
    if (re && ue) sum += dAu;
    // cnt = h + v + h*v, h = le+re, v = ue+de  (>= 3 on this grid)
    float h = (le ? 1.0f : 0.0f) + (re ? 1.0f : 0.0f);
    float v = (ue ? 1.0f : 0.0f) + (de ? 1.0f : 0.0f);
    float cnt = fmaf(h, v, h + v);
    out[OFF_RAD + k] = __fdividef(sum, cnt);

    // --- lens / areas ---
    out[OFF_LEN + 0 * N + k] = re ? dR : 0.0f;
    out[OFF_LEN + 1 * N + k] = rd ? dG : 0.0f;
    out[OFF_LEN + 2 * N + k] = de ? dD : 0.0f;
    out[OFF_LEN + 3 * N + k] = rd ? dA : 0.0f;
    out[OFF_AREA + 0 * N + k] = rd ? a0 : 0.0f;
    out[OFF_AREA + 1 * N + k] = rd ? a1 : 0.0f;
}

// ---------------------------------------------------------------------------
// Launch
// ---------------------------------------------------------------------------
extern "C" void kernel_launch(void* const* d_in, const int* in_sizes, int n_in,
                              void* d_out, int out_size) {
    (void)in_sizes; (void)n_in; (void)out_size;
    const float* cand = (const float*)d_in[1];
    const float* cnrm = (const float*)d_in[2];
    float* out = (float*)d_out;

    k_warp<<<N / TPB, TPB>>>(cand, cnrm, out);
}

// round 16
// speedup vs baseline: 1.5768x; 1.5768x over previous
#include <cuda_runtime.h>
#include <cstdint>

// Fixed problem geometry: H=W=2048, step=2 -> nu=nv=1024, N=2^20 nodes.
constexpr int NU = 1024;
constexpr int NV = 1024;
constexpr int N  = NU * NV;
constexpr int W  = 2048;
constexpr int ROWF = 6 * W;        // floats per pixel row (12288)

// Output layout (floats): pts[3N] nrm[3N] radii[N] lens[4N] areas[2N]
constexpr int OFF_PTS  = 0;
constexpr int OFF_NRM  = 3 * N;
constexpr int OFF_RAD  = 6 * N;
constexpr int OFF_LEN  = 7 * N;
constexpr int OFF_AREA = 11 * N;

constexpr int TPB = 256;

__device__ __forceinline__ float fast_sqrt(float x) {
    return x * rsqrtf(fmaxf(x, 1e-30f));   // x==0 -> 0, not NaN
}

struct F3 { float x, y, z; };

__device__ __forceinline__ float dist3(const F3& a, const F3& b) {
    float dx = a.x - b.x, dy = a.y - b.y, dz = a.z - b.z;
    return fast_sqrt(dx * dx + dy * dy + dz * dz);
}

__device__ __forceinline__ F3 sub3(const F3& a, const F3& b) {
    F3 r; r.x = a.x - b.x; r.y = a.y - b.y; r.z = a.z - b.z; return r;
}

__device__ __forceinline__ float cross_area(const F3& u, const F3& v) {
    float cx = u.y * v.z - u.z * v.y;
    float cy = u.z * v.x - u.x * v.z;
    float cz = u.x * v.y - u.y * v.x;
    return 0.5f * fast_sqrt(cx * cx + cy * cy + cz * cz + 1e-13f);
}

__device__ __forceinline__ F3 loadA(const float* __restrict__ p, int jv, int iu) {
    int off = jv * ROWF + iu * 6;              // anchor pixel, 8B aligned
    float2 ab = *reinterpret_cast<const float2*>(p + off);
    F3 r; r.x = ab.x; r.y = ab.y; r.z = p[off + 2];
    return r;
}

__device__ __forceinline__ F3 shup3(const F3& v) {
    F3 r;
    r.x = __shfl_up_sync(0xffffffffu, v.x, 1);
    r.y = __shfl_up_sync(0xffffffffu, v.y, 1);
    r.z = __shfl_up_sync(0xffffffffu, v.z, 1);
    return r;
}
__device__ __forceinline__ F3 shdn3(const F3& v) {
    F3 r;
    r.x = __shfl_down_sync(0xffffffffu, v.x, 1);
    r.y = __shfl_down_sync(0xffffffffu, v.y, 1);
    r.z = __shfl_down_sync(0xffffffffu, v.z, 1);
    return r;
}

// ---------------------------------------------------------------------------
// One node per thread; warp = 32 consecutive iu within one grid row.
// Neighbor points via warp shuffles; lanes 0/31 patch halos via LDG.
// Natural register allocation (NO min-blocks clamp — regs<39 spills, R15).
// ---------------------------------------------------------------------------
__global__ __launch_bounds__(TPB)
void k_warp(const float* __restrict__ cand,
            const float* __restrict__ cnrm,
            float* __restrict__ out) {
    const int k    = blockIdx.x * TPB + threadIdx.x;
    const int lane = threadIdx.x & 31;
    const int iu   = k & (NU - 1);
    const int jv   = k >> 10;

    const bool re = iu < NU - 1;
    const bool de = jv < NV - 1;
    const bool le = iu > 0;
    const bool ue = jv > 0;
    const bool rd = re && de;

    const int jU = ue ? jv - 1 : 0;    // clamped, flag-guarded
    const int jD = de ? jv + 1 : jv;

    // --- own-column point loads (3 rows) + normal ---
    F3 P0 = loadA(cand, jv, iu);
    F3 PD = loadA(cand, jD, iu);
    F3 PU = loadA(cand, jU, iu);
    F3 NR = loadA(cnrm, jv, iu);

    // pts / nrm out immediately (shortens live ranges)
    {
        const int p3 = OFF_PTS + 3 * k;
        out[p3 + 0] = P0.x; out[p3 + 1] = P0.y; out[p3 + 2] = P0.z;
        const int n3 = OFF_NRM + 3 * k;
        out[n3 + 0] = NR.x; out[n3 + 1] = NR.y; out[n3 + 2] = NR.z;
    }

    // --- neighbor points via shuffles; halo patch by LDG ---
    F3 PR  = shdn3(P0);   // (iu+1, jv)
    F3 PG  = shdn3(PD);   // (iu+1, jD)
    F3 PUR = shdn3(PU);   // (iu+1, jU)
    F3 PUL = shup3(PU);   // (iu-1, jU)
    if (lane == 31) {
        int iR = re ? iu + 1 : iu;     // clamp; re-guarded
        PR  = loadA(cand, jv, iR);
        PG  = loadA(cand, jD, iR);
        PUR = loadA(cand, jU, iR);
    }

    // --- own distances ---
    float dR = dist3(P0, PR);
    float dG = dist3(P0, PG);
    float dD = dist3(P0, PD);
    float dA = dist3(PR, PD);

    // --- left incident distances via shuffle; lane 0 patches all left data ---
    float dRl = __shfl_up_sync(0xffffffffu, dR, 1);   // R[k-1]
    float dAl = __shfl_up_sync(0xffffffffu, dA, 1);   // A[k-1]
    if (lane == 0) {
        int iL = le ? iu - 1 : 0;     // clamp; le-guarded
        F3 Pl  = loadA(cand, jv, iL);
        F3 PDl = loadA(cand, jD, iL);
        PUL    = loadA(cand, jU, iL);
        dRl = dist3(Pl, P0);
        dAl = dist3(P0, PDl);          // A[k-1] = |p(k) - p(k-1+NU)|
    }

    // --- up-row incident distances (ue-guarded) ---
    float dDu  = dist3(PU,  P0);   // D[k-NU]
    float dAu  = dist3(PUR, P0);   // A[k-NU]
    float dGul = dist3(PUL, P0);   // G[k-NU-1]

    // --- areas ---
    float a0 = cross_area(sub3(PR, P0), sub3(PG, P0));
    float a1 = cross_area(sub3(PG, P0), sub3(PD, P0));

    // --- radii: predicated sum; count is {3,5,8} -> select reciprocal ---
    float sum = 0.0f;
    if (re) sum += dR;
    if (rd) sum += dG;
    if (de) sum += dD;
    if (le && de) sum += dAl;
    if (le)       sum += dRl;
    if (le && ue) sum += dGul;
    if (ue)       sum += dDu;
    if (re && ue) sum += dAu;
    bool hfull = le && re;             // both horizontal neighbors
    bool vfull = ue && de;             // both vertical neighbors
    // interior: 8 edges; grid edge (one of the four flags false): 5; corner: 3
    float rcp = (hfull && vfull) ? 0.125f
              : (hfull || vfull) ? 0.2f
                                 : (1.0f / 3.0f);
    out[OFF_RAD + k] = sum * rcp;

    // --- lens / areas ---
    out[OFF_LEN + 0 * N + k] = re ? dR : 0.0f;
    out[OFF_LEN + 1 * N + k] = rd ? dG : 0.0f;
    out[OFF_LEN + 2 * N + k] = de ? dD : 0.0f;
    out[OFF_LEN + 3 * N + k] = rd ? dA : 0.0f;
    out[OFF_AREA + 0 * N + k] = rd ? a0 : 0.0f;
    out[OFF_AREA + 1 * N + k] = rd ? a1 : 0.0f;
}

// ---------------------------------------------------------------------------
// Launch
// ---------------------------------------------------------------------------
extern "C" void kernel_launch(void* const* d_in, const int* in_sizes, int n_in,
                              void* d_out, int out_size) {
    (void)in_sizes; (void)n_in; (void)out_size;
    const float* cand = (const float*)d_in[1];
    const float* cnrm = (const float*)d_in[2];
    float* out = (float*)d_out;

    k_warp<<<N / TPB, TPB>>>(cand, cnrm, out);
}

// round 17
// speedup vs baseline: 1.5792x; 1.0015x over previous
#include <cuda_runtime.h>
#include <cstdint>

// Fixed problem geometry: H=W=2048, step=2 -> nu=nv=1024, N=2^20 nodes.
constexpr int NU = 1024;
constexpr int NV = 1024;
constexpr int N  = NU * NV;
constexpr int W  = 2048;
constexpr int ROWF = 6 * W;        // floats per pixel row (12288)

// Output layout (floats): pts[3N] nrm[3N] radii[N] lens[4N] areas[2N]
constexpr int OFF_PTS  = 0;
constexpr int OFF_NRM  = 3 * N;
constexpr int OFF_RAD  = 6 * N;
constexpr int OFF_LEN  = 7 * N;
constexpr int OFF_AREA = 11 * N;

constexpr int TPB = 256;

__device__ __forceinline__ float fast_sqrt(float x) {
    return x * rsqrtf(fmaxf(x, 1e-30f));   // x==0 -> 0, not NaN
}

struct F3 { float x, y, z; };

__device__ __forceinline__ float dist3(const F3& a, const F3& b) {
    float dx = a.x - b.x, dy = a.y - b.y, dz = a.z - b.z;
    return fast_sqrt(dx * dx + dy * dy + dz * dz);
}

__device__ __forceinline__ F3 sub3(const F3& a, const F3& b) {
    F3 r; r.x = a.x - b.x; r.y = a.y - b.y; r.z = a.z - b.z; return r;
}

__device__ __forceinline__ float cross_area(const F3& u, const F3& v) {
    float cx = u.y * v.z - u.z * v.y;
    float cy = u.z * v.x - u.x * v.z;
    float cz = u.x * v.y - u.y * v.x;
    return 0.5f * fast_sqrt(cx * cx + cy * cy + cz * cz + 1e-13f);
}

__device__ __forceinline__ F3 loadA(const float* __restrict__ p, int jv, int iu) {
    int off = jv * ROWF + iu * 6;              // anchor pixel, 8B aligned
    float2 ab = *reinterpret_cast<const float2*>(p + off);
    F3 r; r.x = ab.x; r.y = ab.y; r.z = p[off + 2];
    return r;
}

__device__ __forceinline__ F3 shup3(const F3& v) {
    F3 r;
    r.x = __shfl_up_sync(0xffffffffu, v.x, 1);
    r.y = __shfl_up_sync(0xffffffffu, v.y, 1);
    r.z = __shfl_up_sync(0xffffffffu, v.z, 1);
    return r;
}
__device__ __forceinline__ F3 shdn3(const F3& v) {
    F3 r;
    r.x = __shfl_down_sync(0xffffffffu, v.x, 1);
    r.y = __shfl_down_sync(0xffffffffu, v.y, 1);
    r.z = __shfl_down_sync(0xffffffffu, v.z, 1);
    return r;
}

// ---------------------------------------------------------------------------
// One node per thread; warp = 32 consecutive iu within one grid row.
// Neighbor points via warp shuffles. Up-row diagonal distances are computed
// as cross-lane candidates (tA, tG) and exchanged as SCALARS, eliminating the
// PUL/PUR point shuffles and their 6 live registers.
// Natural register allocation (no min-blocks clamp: forcing below ~39 spills).
// ---------------------------------------------------------------------------
__global__ __launch_bounds__(TPB)
void k_warp(const float* __restrict__ cand,
            const float* __restrict__ cnrm,
            float* __restrict__ out) {
    const int k    = blockIdx.x * TPB + threadIdx.x;
    const int lane = threadIdx.x & 31;
    const int iu   = k & (NU - 1);
    const int jv   = k >> 10;

    const bool re = iu < NU - 1;
    const bool de = jv < NV - 1;
    const bool le = iu > 0;
    const bool ue = jv > 0;
    const bool rd = re && de;

    const int jU = ue ? jv - 1 : 0;    // clamped, flag-guarded
    const int jD = de ? jv + 1 : jv;

    // --- own-column point loads (3 rows) + normal ---
    F3 P0 = loadA(cand, jv, iu);
    F3 PD = loadA(cand, jD, iu);
    F3 PU = loadA(cand, jU, iu);
    F3 NR = loadA(cnrm, jv, iu);

    // pts / nrm out immediately (shortens live ranges)
    {
        const int p3 = OFF_PTS + 3 * k;
        out[p3 + 0] = P0.x; out[p3 + 1] = P0.y; out[p3 + 2] = P0.z;
        const int n3 = OFF_NRM + 3 * k;
        out[n3 + 0] = NR.x; out[n3 + 1] = NR.y; out[n3 + 2] = NR.z;
    }

    // --- neighbor points via shuffles ---
    F3 PR  = shdn3(P0);   // (iu+1, jv)
    F3 PG  = shdn3(PD);   // (iu+1, jD)
    F3 PLu = shup3(P0);   // (iu-1, jv), used only to form tA
    if (lane == 31) {
        int iR = re ? iu + 1 : iu;     // clamp; re-guarded
        PR  = loadA(cand, jv, iR);
        PG  = loadA(cand, jD, iR);
    }

    // --- own distances ---
    float dR = dist3(P0, PR);
    float dG = dist3(P0, PG);
    float dD = dist3(P0, PD);
    float dA = dist3(PR, PD);
    float dDu = dist3(PU, P0);         // D[k-NU] (ue-guarded)

    // --- cross-lane up-diagonal candidates, exchanged as scalars ---
    // tA_j = |PU_j - P0_{j-1}|  ->  lane l's A[k-NU]   = tA_{l+1}
    // tG_j = |PU_j - P0_{j+1}|  ->  lane l's G[k-NU-1] = tG_{l-1}
    float tA = dist3(PU, PLu);         // garbage at lane 0 (consumed by nobody)
    float tG = dist3(PU, PR);          // lane31's value consumed by nobody
    float dAu  = __shfl_down_sync(0xffffffffu, tA, 1);
    float dGul = __shfl_up_sync(0xffffffffu, tG, 1);

    // --- left incident distances via shuffle ---
    float dRl = __shfl_up_sync(0xffffffffu, dR, 1);   // R[k-1]
    float dAl = __shfl_up_sync(0xffffffffu, dA, 1);   // A[k-1]

    // --- halo patches (clamped indices; all uses flag-guarded) ---
    if (lane == 31) {
        int iR = re ? iu + 1 : iu;
        dAu = dist3(loadA(cand, jU, iR), P0);         // A[k-NU]
    }
    if (lane == 0) {
        int iL = le ? iu - 1 : 0;
        F3 Pl  = loadA(cand, jv, iL);
        F3 PDl = loadA(cand, jD, iL);
        F3 PUl = loadA(cand, jU, iL);
        dRl  = dist3(Pl, P0);                          // R[k-1]
        dAl  = dist3(P0, PDl);                         // A[k-1]
        dGul = dist3(PUl, P0);                         // G[k-NU-1]
    }

    // --- areas ---
    float a0 = cross_area(sub3(PR, P0), sub3(PG, P0));
    float a1 = cross_area(sub3(PG, P0), sub3(PD, P0));

    // --- radii: predicated sum; count in {3,5,8} -> select reciprocal ---
    float sum = 0.0f;
    if (re) sum += dR;
    if (rd) sum += dG;
    if (de) sum += dD;
    if (le && de) sum += dAl;
    if (le)       sum += dRl;
    if (le && ue) sum += dGul;
    if (ue)       sum += dDu;
    if (re && ue) sum += dAu;
    bool hfull = le && re;
    bool vfull = ue && de;
    float rcp = (hfull && vfull) ? 0.125f
              : (hfull || vfull) ? 0.2f
                                 : (1.0f / 3.0f);
    out[OFF_RAD + k] = sum * rcp;

    // --- lens / areas ---
    out[OFF_LEN + 0 * N + k] = re ? dR : 0.0f;
    out[OFF_LEN + 1 * N + k] = rd ? dG : 0.0f;
    out[OFF_LEN + 2 * N + k] = de ? dD : 0.0f;
    out[OFF_LEN + 3 * N + k] = rd ? dA : 0.0f;
    out[OFF_AREA + 0 * N + k] = rd ? a0 : 0.0f;
    out[OFF_AREA + 1 * N + k] = rd ? a1 : 0.0f;
}

// ---------------------------------------------------------------------------
// Launch
// ---------------------------------------------------------------------------
extern "C" void kernel_launch(void* const* d_in, const int* in_sizes, int n_in,
                              void* d_out, int out_size) {
    (void)in_sizes; (void)n_in; (void)out_size;
    const float* cand = (const float*)d_in[1];
    const float* cnrm = (const float*)d_in[2];
    float* out = (float*)d_out;

    k_warp<<<N / TPB, TPB>>>(cand, cnrm, out);
}